// round 4
// baseline (speedup 1.0000x reference)
#include <cuda_runtime.h>
#include <math.h>
#include <stdint.h>

#define NCLS   80
#define KMAX   1000
#define CAP    16384
#define MAXM   50176
#define NPAD   1024

// ---------------- scratch (no allocations allowed) ----------------
static __device__ unsigned long long g_key[MAXM];
static __device__ int                g_label[MAXM];
static __device__ unsigned int       g_hist[65536];
static __device__ unsigned int       g_hist2[65536];
static __device__ int                g_misc[8]; // [0]=cand cnt [1]=bin T [2]=strictly-above cnt [3]=thresh32
static __device__ unsigned long long g_cand[CAP];
static __device__ int                g_topidx[NPAD];
static __device__ float              g_topscore[NPAD];
static __device__ float              g_box[NPAD * 4];
static __device__ float              g_boxoff[NPAD * 4];
static __device__ float              g_area[NPAD];
static __device__ int                g_toplab[NPAD];
static __device__ unsigned int       g_validmask[32];
static __device__ unsigned int       g_keepmask[32];
static __device__ unsigned int       g_mask[NPAD * 32];

// ---------------- helpers ----------------
// XLA logistic = 0.5 + 0.5 * tanh(0.5*x), with XLA's rational tanh approx.
// All ops via _rn intrinsics so fmad contraction / fast-math cannot change bits.
__device__ __forceinline__ float xla_sigmoid(float x) {
    float t  = __fmul_rn(0.5f, x);
    float tc = fminf(fmaxf(t, -7.90531110763549805f), 7.90531110763549805f);
    float x2 = __fmul_rn(tc, tc);
    float p = -2.76076847742355e-16f;
    p = __fadd_rn(__fmul_rn(p, x2), 2.00018790482477e-13f);
    p = __fadd_rn(__fmul_rn(p, x2), -8.60467152213735e-11f);
    p = __fadd_rn(__fmul_rn(p, x2), 5.12229709037114e-08f);
    p = __fadd_rn(__fmul_rn(p, x2), 1.48572235717979e-05f);
    p = __fadd_rn(__fmul_rn(p, x2), 6.37261928875436e-04f);
    p = __fadd_rn(__fmul_rn(p, x2), 4.89352455891786e-03f);
    float num = __fmul_rn(tc, p);
    float q = 1.19825839466702e-06f;
    q = __fadd_rn(__fmul_rn(q, x2), 1.18534705686654e-04f);
    q = __fadd_rn(__fmul_rn(q, x2), 2.26843463243900e-03f);
    q = __fadd_rn(__fmul_rn(q, x2), 4.89352518554385e-03f);
    float th = __fdiv_rn(num, q);
    th = (fabsf(t) < 0.0004f) ? t : th;
    return __fadd_rn(0.5f, __fmul_rn(0.5f, th));
}

__device__ __forceinline__ unsigned int f2u_mono(float f) {
    unsigned int u = __float_as_uint(f);
    return (u & 0x80000000u) ? ~u : (u | 0x80000000u);
}
__device__ __forceinline__ float u2f_mono(unsigned int u) {
    unsigned int b = (u & 0x80000000u) ? (u & 0x7FFFFFFFu) : ~u;
    return __uint_as_float(b);
}
__device__ __forceinline__ int read_dim(const void* p) {
    int v = *(const int*)p;
    if (v > 0 && v < (1 << 20)) return v;
    return (int)(*(const float*)p);
}

// ---------------- kernels ----------------
__global__ void zero_kernel() {
    int t = blockIdx.x * blockDim.x + threadIdx.x;
    for (int k = t; k < 65536; k += gridDim.x * blockDim.x) { g_hist[k] = 0u; g_hist2[k] = 0u; }
    if (t < 8) g_misc[t] = 0;
}

// one warp per row: raw-logit max/argmax (sigmoid monotone -> same winner),
// then ONE exact XLA sigmoid per row so sort keys tie exactly like the reference.
__global__ void score_kernel(const float* __restrict__ cls, int M) {
    int warp = (blockIdx.x * blockDim.x + threadIdx.x) >> 5;
    int lane = threadIdx.x & 31;
    if (warp >= M || warp >= MAXM) return;
    const float* row = cls + (long long)warp * NCLS;
    float best = -1e30f; int bidx = NCLS;
    #pragma unroll
    for (int k = 0; k < 3; k++) {
        int c = lane + 32 * k;
        if (c < NCLS) {
            float s = __ldg(row + c);
            if (s > best) { best = s; bidx = c; }
        }
    }
    #pragma unroll
    for (int off = 16; off > 0; off >>= 1) {
        float ob = __shfl_down_sync(0xffffffffu, best, off);
        int   oi = __shfl_down_sync(0xffffffffu, bidx, off);
        if (ob > best || (ob == best && oi < bidx)) { best = ob; bidx = oi; }
    }
    if (lane == 0) {
        float sig = xla_sigmoid(best);           // exact reference score
        unsigned int u = f2u_mono(sig);
        unsigned long long key =
            ((unsigned long long)u << 32) | (unsigned long long)(0xFFFFFFFFu - (unsigned int)warp);
        g_key[warp]  = key;
        g_label[warp] = bidx;
        atomicAdd(&g_hist[u >> 16], 1u);
    }
}

// level-1: threshold bin T (largest bin with suffix-count >= K) + count strictly above it
__global__ void scan_kernel(int K) {
    __shared__ unsigned int part[1024];
    int t = threadIdx.x;
    unsigned int s = 0;
    int hi = 65535 - t * 64;
    for (int k = 0; k < 64; k++) s += g_hist[hi - k];
    part[t] = s;
    __syncthreads();
    if (t == 0) {
        unsigned int cumAbove = 0; int chunk = 1023;
        for (int c = 0; c < 1024; c++) {
            if (cumAbove + part[c] >= (unsigned int)K) { chunk = c; break; }
            cumAbove += part[c];
        }
        int topbin = 65535 - chunk * 64;
        unsigned int cum = cumAbove;
        int T = topbin - 63; if (T < 0) T = 0;
        for (int k = 0; k < 64; k++) {
            unsigned int h = g_hist[topbin - k];
            if (cum + h >= (unsigned int)K) { T = topbin - k; break; }
            cum += h;
        }
        g_misc[1] = T;
        g_misc[2] = (int)cum;   // strictly above bin T
    }
}

// level-2: fine histogram of low 16 bits within threshold bin
__global__ void hist2_kernel(int M) {
    int T = g_misc[1];
    for (int i = blockIdx.x * blockDim.x + threadIdx.x; i < M; i += gridDim.x * blockDim.x) {
        unsigned int u = (unsigned int)(__ldg(&g_key[i]) >> 32);
        if ((int)(u >> 16) == T) atomicAdd(&g_hist2[u & 0xFFFFu], 1u);
    }
}

// level-2 scan: exact 32-bit threshold so candidates ~= K + ties
__global__ void scan2_kernel(int K) {
    __shared__ unsigned int part[1024];
    int t = threadIdx.x;
    unsigned int s = 0;
    int hi = 65535 - t * 64;
    for (int k = 0; k < 64; k++) s += g_hist2[hi - k];
    part[t] = s;
    __syncthreads();
    if (t == 0) {
        unsigned int above = (unsigned int)g_misc[2];
        unsigned int cum = above; int chunk = 1023;
        for (int c = 0; c < 1024; c++) {
            if (cum + part[c] >= (unsigned int)K) { chunk = c; break; }
            cum += part[c];
        }
        int topbin = 65535 - chunk * 64;
        int L = 0;
        for (int k = 0; k < 64; k++) {
            cum += g_hist2[topbin - k];
            if (cum >= (unsigned int)K) { L = topbin - k; break; }
        }
        g_misc[3] = (int)(((unsigned int)g_misc[1] << 16) | (unsigned int)L);
    }
}

__global__ void compact_kernel(int M) {
    unsigned int thr = (unsigned int)g_misc[3];
    for (int i = blockIdx.x * blockDim.x + threadIdx.x; i < M; i += gridDim.x * blockDim.x) {
        unsigned long long key = __ldg(&g_key[i]);
        if ((unsigned int)(key >> 32) >= thr) {
            int pos = atomicAdd(&g_misc[0], 1);
            if (pos < CAP) g_cand[pos] = key;
        }
    }
}

// exact stable ranking of ~K candidates (distinct 64-bit keys)
__global__ void rank_kernel(int K) {
    extern __shared__ unsigned long long sh64[];
    int t = threadIdx.x;
    int n = g_misc[0]; if (n > CAP) n = CAP;
    for (int i = t; i < n; i += blockDim.x) sh64[i] = g_cand[i];
    __syncthreads();
    for (int j = t; j < n; j += blockDim.x) {
        unsigned long long kj = sh64[j];
        int rank = 0;
        for (int k = 0; k < n; k++) rank += (sh64[k] > kj) ? 1 : 0;
        if (rank < K) {
            g_topscore[rank] = u2f_mono((unsigned int)(kj >> 32));   // sigmoid score
            g_topidx[rank]   = (int)(0xFFFFFFFFu - (unsigned int)(kj & 0xFFFFFFFFull));
        }
    }
}

// decode boxes + class-offset boxes + areas + valid mask
__global__ void decode_kernel(const float* __restrict__ regp,
                              const float* __restrict__ anc,
                              const void* fw_ptr, int A, int K) {
    int r = threadIdx.x;
    int fw = read_dim(fw_ptr);
    bool active = (r < K);
    bool valid = false;
    if (active) {
        int idx = g_topidx[r];
        int lab = g_label[idx];
        float score = g_topscore[r];
        int cell = idx / A, a = idx - cell * A;
        int ix = cell % fw, iy = cell / fw;
        float ax = (ix + 0.5f) * 32.0f;
        float ay = (iy + 0.5f) * 32.0f;
        float aw = anc[a * 2 + 0], ah = anc[a * 2 + 1];
        float r0 = regp[idx * 4 + 0], r1 = regp[idx * 4 + 1];
        float r2 = regp[idx * 4 + 2], r3 = regp[idx * 4 + 3];
        float ox = fminf(fmaxf(__fmul_rn(r0, aw), -32.0f), 32.0f);
        float oy = fminf(fmaxf(__fmul_rn(r1, ah), -32.0f), 32.0f);
        float cx = __fadd_rn(ax, ox);
        float cy = __fadd_rn(ay, oy);
        const float SCALE_CLAMP = (float)4.1351665567423560;
        float ew = __fmul_rn(aw, expf(fminf(r2, SCALE_CLAMP)));
        float eh = __fmul_rn(ah, expf(fminf(r3, SCALE_CLAMP)));
        float hw = __fmul_rn(0.5f, ew), hh = __fmul_rn(0.5f, eh);
        float b0 = __fadd_rn(cx, -hw), b1 = __fadd_rn(cy, -hh);
        float b2 = __fadd_rn(cx,  hw), b3 = __fadd_rn(cy,  hh);
        float off = (float)lab * 100000.0f;
        float o0 = __fadd_rn(b0, off), o1 = __fadd_rn(b1, off);
        float o2 = __fadd_rn(b2, off), o3 = __fadd_rn(b3, off);
        g_box[r * 4 + 0] = b0; g_box[r * 4 + 1] = b1;
        g_box[r * 4 + 2] = b2; g_box[r * 4 + 3] = b3;
        g_boxoff[r * 4 + 0] = o0; g_boxoff[r * 4 + 1] = o1;
        g_boxoff[r * 4 + 2] = o2; g_boxoff[r * 4 + 3] = o3;
        g_area[r] = __fmul_rn(__fadd_rn(o2, -o0), __fadd_rn(o3, -o1));
        g_toplab[r] = lab;
        valid = (score >= 0.05f);
    }
    unsigned int bal = __ballot_sync(0xffffffffu, active && valid);
    if ((threadIdx.x & 31) == 0) g_validmask[threadIdx.x >> 5] = bal;
}

// one block per row i: 32-word suppression bitmask (j>i && iou>0.6)
// division-free: iou > 0.6  <=>  inter > 0.6*den (den > 0)
__global__ void iou_kernel(int K) {
    int i = blockIdx.x;
    __shared__ float bi[5];
    if (threadIdx.x < 4) bi[threadIdx.x] = g_boxoff[i * 4 + threadIdx.x];
    if (threadIdx.x == 0) bi[4] = g_area[i];
    __syncthreads();
    float x1i = bi[0], y1i = bi[1], x2i = bi[2], y2i = bi[3], ai = bi[4];
    for (int j = threadIdx.x; j < NPAD; j += blockDim.x) {
        bool pred = false;
        if (j < K && j > i) {
            float x1j = g_boxoff[j * 4 + 0], y1j = g_boxoff[j * 4 + 1];
            float x2j = g_boxoff[j * 4 + 2], y2j = g_boxoff[j * 4 + 3];
            float xx1 = fmaxf(x1i, x1j), yy1 = fmaxf(y1i, y1j);
            float xx2 = fminf(x2i, x2j), yy2 = fminf(y2i, y2j);
            float iw = fmaxf(1e-28f, __fadd_rn(xx2, -xx1));
            float ih = fmaxf(1e-28f, __fadd_rn(yy2, -yy1));
            float inter = __fmul_rn(iw, ih);
            float den = __fadd_rn(__fadd_rn(__fadd_rn(ai, g_area[j]), -inter), 1e-14f);
            pred = (inter > __fmul_rn(0.6f, den));
        }
        unsigned int b = __ballot_sync(0xffffffffu, pred);
        if ((threadIdx.x & 31) == 0) g_mask[i * 32 + (j >> 5)] = b;
    }
}

// single-warp greedy NMS scan over 32x32 chunks
__global__ void nms_scan_kernel(int K) {
    extern __shared__ unsigned int sh[];
    int lane = threadIdx.x;
    int totw = K * 32;
    for (int k = lane; k < totw; k += 32) sh[k] = g_mask[k];
    __syncwarp();
    unsigned int remv = 0;
    unsigned int valid = g_validmask[lane];
    unsigned int keepw = 0;
    int nch = (K + 31) >> 5;
    for (int c = 0; c < nch; ++c) {
        int base = c << 5;
        int cnt = K - base; if (cnt > 32) cnt = 32;
        unsigned int d[32];
        #pragma unroll
        for (int i = 0; i < 32; i++) d[i] = (i < cnt) ? sh[(base + i) * 32 + c] : 0u;
        unsigned int supp   = __shfl_sync(0xffffffffu, remv, c);
        unsigned int vC     = __shfl_sync(0xffffffffu, valid, c);
        unsigned int aliveM = 0;
        #pragma unroll
        for (int i = 0; i < 32; i++) {
            unsigned int bit = 1u << i;
            if ((vC & bit) && !(supp & bit)) { aliveM |= bit; supp |= d[i]; }
        }
        unsigned int m = aliveM;
        while (m) {
            int i = __ffs(m) - 1; m &= m - 1;
            remv |= sh[(base + i) * 32 + lane];
        }
        if (lane == c) keepw = aliveM;
    }
    g_keepmask[lane] = keepw;
}

__global__ void output_kernel(float* __restrict__ out, int out_size,
                              const void* fh_ptr, const void* fw_ptr, int K) {
    int t = blockIdx.x * blockDim.x + threadIdx.x;
    if (t < K) {
        bool keep = (g_keepmask[t >> 5] >> (t & 31)) & 1u;
        float m = keep ? 1.0f : 0.0f;
        float W = (float)(read_dim(fw_ptr) * 32);
        float H = (float)(read_dim(fh_ptr) * 32);
        float b0 = g_box[t * 4 + 0], b1 = g_box[t * 4 + 1];
        float b2 = g_box[t * 4 + 2], b3 = g_box[t * 4 + 3];
        float n0 = fminf(fmaxf(__fdiv_rn(b0, W), 0.0f), 1.0f);
        float n1 = fminf(fmaxf(__fdiv_rn(b1, H), 0.0f), 1.0f);
        float n2 = fminf(fmaxf(__fdiv_rn(b2, W), 0.0f), 1.0f);
        float n3 = fminf(fmaxf(__fdiv_rn(b3, H), 0.0f), 1.0f);
        out[t * 4 + 0] = n0 * m;
        out[t * 4 + 1] = n1 * m;
        out[t * 4 + 2] = n2 * m;
        out[t * 4 + 3] = n3 * m;
        out[4 * K + t] = g_topscore[t] * m;
        out[5 * K + t] = keep ? (float)g_toplab[t] : -1.0f;
        out[6 * K + t] = m;
    }
    for (int z = 7 * K + t; z < out_size; z += gridDim.x * blockDim.x) out[z] = 0.0f;
}

// ---------------- launch ----------------
extern "C" void kernel_launch(void* const* d_in, const int* in_sizes, int n_in,
                              void* d_out, int out_size) {
    const float* cls = (const float*)d_in[0];
    const float* reg = (const float*)d_in[1];
    const float* anc = (const float*)d_in[2];
    const void*  fh  = d_in[3];
    const void*  fw  = d_in[4];

    int M = in_sizes[0] / NCLS;
    int A = in_sizes[2] / 2;
    int K = (M < KMAX) ? M : KMAX;

    cudaFuncSetAttribute(rank_kernel, cudaFuncAttributeMaxDynamicSharedMemorySize, CAP * 8);
    cudaFuncSetAttribute(nms_scan_kernel, cudaFuncAttributeMaxDynamicSharedMemorySize, NPAD * 32 * 4);

    zero_kernel<<<64, 256>>>();
    score_kernel<<<(M + 3) / 4, 128>>>(cls, M);
    scan_kernel<<<1, 1024>>>(K);
    hist2_kernel<<<(M + 255) / 256, 256>>>(M);
    scan2_kernel<<<1, 1024>>>(K);
    compact_kernel<<<(M + 255) / 256, 256>>>(M);
    rank_kernel<<<1, 1024, CAP * 8>>>(K);
    decode_kernel<<<1, 1024>>>(reg, anc, fw, A, K);
    iou_kernel<<<K, 128>>>(K);
    nms_scan_kernel<<<1, 32, K * 32 * 4>>>(K);
    output_kernel<<<8, 1024>>>((float*)d_out, out_size, fh, fw, K);
}

// round 16
// speedup vs baseline: 1.6119x; 1.6119x over previous
#include <cuda_runtime.h>
#include <math.h>
#include <stdint.h>

#define NCLS   80
#define KMAX   1000
#define CAP    4096
#define MAXM   50176
#define NPAD   1024

// ---------------- scratch (no allocations allowed) ----------------
static __device__ unsigned int       g_u32[MAXM];     // monotone sigmoid bits per row
static __device__ int                g_label[MAXM];
static __device__ unsigned int       g_hist[65536];
static __device__ unsigned int       g_hist2[65536];
static __device__ int                g_misc[8]; // [0]=cand cnt [1]=bin T [2]=strictly-above cnt [3]=thresh32
static __device__ unsigned long long g_cand[CAP];
static __device__ int                g_topidx[NPAD];
static __device__ float              g_topscore[NPAD];
static __device__ float              g_box[NPAD * 4];
static __device__ float              g_boxoff[NPAD * 4];
static __device__ float              g_area[NPAD];
static __device__ int                g_toplab[NPAD];
static __device__ unsigned int       g_validmask[32];
static __device__ unsigned int       g_keepmask[32];
static __device__ unsigned int       g_mask[NPAD * 32];

// ---------------- helpers ----------------
// XLA logistic = 0.5 + 0.5 * tanh(0.5*x), with XLA's rational tanh approx.
// All ops via _rn intrinsics so fmad contraction / fast-math cannot change bits.
__device__ __forceinline__ float xla_sigmoid(float x) {
    float t  = __fmul_rn(0.5f, x);
    float tc = fminf(fmaxf(t, -7.90531110763549805f), 7.90531110763549805f);
    float x2 = __fmul_rn(tc, tc);
    float p = -2.76076847742355e-16f;
    p = __fadd_rn(__fmul_rn(p, x2), 2.00018790482477e-13f);
    p = __fadd_rn(__fmul_rn(p, x2), -8.60467152213735e-11f);
    p = __fadd_rn(__fmul_rn(p, x2), 5.12229709037114e-08f);
    p = __fadd_rn(__fmul_rn(p, x2), 1.48572235717979e-05f);
    p = __fadd_rn(__fmul_rn(p, x2), 6.37261928875436e-04f);
    p = __fadd_rn(__fmul_rn(p, x2), 4.89352455891786e-03f);
    float num = __fmul_rn(tc, p);
    float q = 1.19825839466702e-06f;
    q = __fadd_rn(__fmul_rn(q, x2), 1.18534705686654e-04f);
    q = __fadd_rn(__fmul_rn(q, x2), 2.26843463243900e-03f);
    q = __fadd_rn(__fmul_rn(q, x2), 4.89352518554385e-03f);
    float th = __fdiv_rn(num, q);
    th = (fabsf(t) < 0.0004f) ? t : th;
    return __fadd_rn(0.5f, __fmul_rn(0.5f, th));
}

__device__ __forceinline__ unsigned int f2u_mono(float f) {
    unsigned int u = __float_as_uint(f);
    return (u & 0x80000000u) ? ~u : (u | 0x80000000u);
}
__device__ __forceinline__ float u2f_mono(unsigned int u) {
    unsigned int b = (u & 0x80000000u) ? (u & 0x7FFFFFFFu) : ~u;
    return __uint_as_float(b);
}
__device__ __forceinline__ int read_dim(const void* p) {
    int v = *(const int*)p;
    if (v > 0 && v < (1 << 20)) return v;
    return (int)(*(const float*)p);
}

// ---------------- kernels ----------------
__global__ void zero_kernel() {
    int t = blockIdx.x * blockDim.x + threadIdx.x;
    for (int k = t; k < 65536; k += gridDim.x * blockDim.x) { g_hist[k] = 0u; g_hist2[k] = 0u; }
    if (t < 8) g_misc[t] = 0;
}

// one warp per row: raw-logit max/argmax (sigmoid monotone -> same winner),
// then ONE exact XLA sigmoid per row so sort keys tie exactly like the reference.
__global__ void score_kernel(const float* __restrict__ cls, int M) {
    int warp = (blockIdx.x * blockDim.x + threadIdx.x) >> 5;
    int lane = threadIdx.x & 31;
    if (warp >= M || warp >= MAXM) return;
    const float* row = cls + (long long)warp * NCLS;
    float best = -1e30f; int bidx = NCLS;
    #pragma unroll
    for (int k = 0; k < 3; k++) {
        int c = lane + 32 * k;
        if (c < NCLS) {
            float s = __ldg(row + c);
            if (s > best) { best = s; bidx = c; }
        }
    }
    #pragma unroll
    for (int off = 16; off > 0; off >>= 1) {
        float ob = __shfl_down_sync(0xffffffffu, best, off);
        int   oi = __shfl_down_sync(0xffffffffu, bidx, off);
        if (ob > best || (ob == best && oi < bidx)) { best = ob; bidx = oi; }
    }
    if (lane == 0) {
        float sig = xla_sigmoid(best);           // exact reference score
        unsigned int u = f2u_mono(sig);
        g_u32[warp]  = u;
        g_label[warp] = bidx;
        atomicAdd(&g_hist[u >> 16], 1u);
    }
}

// level-1: parallel suffix scan over 1024 chunks of 64 bins (descending score order)
__global__ void scan_kernel(int K) {
    __shared__ unsigned int part[1024];
    int t = threadIdx.x;
    unsigned int s = 0;
    int hi = 65535 - t * 64;                 // chunk t covers bins [hi-63, hi]
    #pragma unroll 8
    for (int k = 0; k < 64; k++) s += g_hist[hi - k];
    part[t] = s;
    __syncthreads();
    unsigned int v = s;
    #pragma unroll
    for (int off = 1; off < 1024; off <<= 1) {
        unsigned int u = (t >= off) ? part[t - off] : 0u;
        __syncthreads();
        v += u;
        part[t] = v;
        __syncthreads();
    }
    unsigned int incl = v, excl = v - s;
    if (incl >= (unsigned int)K && excl < (unsigned int)K) {
        unsigned int cum = excl;
        int topbin = 65535 - t * 64;
        int T = topbin - 63; if (T < 0) T = 0;
        for (int k = 0; k < 64; k++) {
            unsigned int h = g_hist[topbin - k];
            if (cum + h >= (unsigned int)K) { T = topbin - k; break; }
            cum += h;
        }
        g_misc[1] = T;
        g_misc[2] = (int)cum;   // strictly above bin T
    }
}

// level-2: fine histogram of low 16 bits within threshold bin
__global__ void hist2_kernel(int M) {
    int T = g_misc[1];
    for (int i = blockIdx.x * blockDim.x + threadIdx.x; i < M; i += gridDim.x * blockDim.x) {
        unsigned int u = __ldg(&g_u32[i]);
        if ((int)(u >> 16) == T) atomicAdd(&g_hist2[u & 0xFFFFu], 1u);
    }
}

// level-2 scan: exact 32-bit threshold so candidates ~= K + ties
__global__ void scan2_kernel(int K) {
    __shared__ unsigned int part[1024];
    int t = threadIdx.x;
    unsigned int above = (unsigned int)g_misc[2];
    unsigned int s = 0;
    int hi = 65535 - t * 64;
    #pragma unroll 8
    for (int k = 0; k < 64; k++) s += g_hist2[hi - k];
    part[t] = s;
    __syncthreads();
    unsigned int v = s;
    #pragma unroll
    for (int off = 1; off < 1024; off <<= 1) {
        unsigned int u = (t >= off) ? part[t - off] : 0u;
        __syncthreads();
        v += u;
        part[t] = v;
        __syncthreads();
    }
    unsigned int incl = above + v, excl = above + v - s;
    if (incl >= (unsigned int)K && excl < (unsigned int)K) {
        unsigned int cum = excl;
        int topbin = 65535 - t * 64;
        int L = topbin - 63; if (L < 0) L = 0;
        for (int k = 0; k < 64; k++) {
            unsigned int h = g_hist2[topbin - k];
            if (cum + h >= (unsigned int)K) { L = topbin - k; break; }
            cum += h;
        }
        g_misc[3] = (int)(((unsigned int)g_misc[1] << 16) | (unsigned int)L);
    }
}

// compact: reconstruct 64-bit key from (score bits, index) only for survivors
__global__ void compact_kernel(int M) {
    unsigned int thr = (unsigned int)g_misc[3];
    for (int i = blockIdx.x * blockDim.x + threadIdx.x; i < M; i += gridDim.x * blockDim.x) {
        unsigned int u = __ldg(&g_u32[i]);
        if (u >= thr) {
            int pos = atomicAdd(&g_misc[0], 1);
            if (pos < CAP)
                g_cand[pos] = ((unsigned long long)u << 32)
                            | (unsigned long long)(0xFFFFFFFFu - (unsigned int)i);
        }
    }
}

// exact stable ranking of ~K candidates; j-work spread over gridDim blocks,
// each block caches all candidates in its own shared memory.
__global__ void rank_kernel(int K) {
    extern __shared__ unsigned long long sh64[];
    int t = threadIdx.x;
    int n = g_misc[0]; if (n > CAP) n = CAP;
    for (int i = t; i < n; i += blockDim.x) sh64[i] = g_cand[i];
    __syncthreads();
    for (int j = blockIdx.x * blockDim.x + t; j < n; j += gridDim.x * blockDim.x) {
        unsigned long long kj = sh64[j];
        int rank = 0;
        for (int k = 0; k < n; k++) rank += (sh64[k] > kj) ? 1 : 0;
        if (rank < K) {
            g_topscore[rank] = u2f_mono((unsigned int)(kj >> 32));   // sigmoid score
            g_topidx[rank]   = (int)(0xFFFFFFFFu - (unsigned int)(kj & 0xFFFFFFFFull));
        }
    }
}

// decode boxes + class-offset boxes + areas + valid mask
__global__ void decode_kernel(const float* __restrict__ regp,
                              const float* __restrict__ anc,
                              const void* fw_ptr, int A, int K) {
    int r = threadIdx.x;
    int fw = read_dim(fw_ptr);
    bool active = (r < K);
    bool valid = false;
    if (active) {
        int idx = g_topidx[r];
        int lab = g_label[idx];
        float score = g_topscore[r];
        int cell = idx / A, a = idx - cell * A;
        int ix = cell % fw, iy = cell / fw;
        float ax = (ix + 0.5f) * 32.0f;
        float ay = (iy + 0.5f) * 32.0f;
        float aw = anc[a * 2 + 0], ah = anc[a * 2 + 1];
        float r0 = regp[idx * 4 + 0], r1 = regp[idx * 4 + 1];
        float r2 = regp[idx * 4 + 2], r3 = regp[idx * 4 + 3];
        float ox = fminf(fmaxf(__fmul_rn(r0, aw), -32.0f), 32.0f);
        float oy = fminf(fmaxf(__fmul_rn(r1, ah), -32.0f), 32.0f);
        float cx = __fadd_rn(ax, ox);
        float cy = __fadd_rn(ay, oy);
        const float SCALE_CLAMP = (float)4.1351665567423560;
        float ew = __fmul_rn(aw, expf(fminf(r2, SCALE_CLAMP)));
        float eh = __fmul_rn(ah, expf(fminf(r3, SCALE_CLAMP)));
        float hw = __fmul_rn(0.5f, ew), hh = __fmul_rn(0.5f, eh);
        float b0 = __fadd_rn(cx, -hw), b1 = __fadd_rn(cy, -hh);
        float b2 = __fadd_rn(cx,  hw), b3 = __fadd_rn(cy,  hh);
        float off = (float)lab * 100000.0f;
        float o0 = __fadd_rn(b0, off), o1 = __fadd_rn(b1, off);
        float o2 = __fadd_rn(b2, off), o3 = __fadd_rn(b3, off);
        g_box[r * 4 + 0] = b0; g_box[r * 4 + 1] = b1;
        g_box[r * 4 + 2] = b2; g_box[r * 4 + 3] = b3;
        g_boxoff[r * 4 + 0] = o0; g_boxoff[r * 4 + 1] = o1;
        g_boxoff[r * 4 + 2] = o2; g_boxoff[r * 4 + 3] = o3;
        g_area[r] = __fmul_rn(__fadd_rn(o2, -o0), __fadd_rn(o3, -o1));
        g_toplab[r] = lab;
        valid = (score >= 0.05f);
    }
    unsigned int bal = __ballot_sync(0xffffffffu, active && valid);
    if ((threadIdx.x & 31) == 0) g_validmask[threadIdx.x >> 5] = bal;
}

// one block per row i: 32-word suppression bitmask (j>i && iou>0.6)
// division-free: iou > 0.6  <=>  inter > 0.6*den (den > 0)
__global__ void iou_kernel(int K) {
    int i = blockIdx.x;
    __shared__ float bi[5];
    if (threadIdx.x < 4) bi[threadIdx.x] = g_boxoff[i * 4 + threadIdx.x];
    if (threadIdx.x == 0) bi[4] = g_area[i];
    __syncthreads();
    float x1i = bi[0], y1i = bi[1], x2i = bi[2], y2i = bi[3], ai = bi[4];
    for (int j = threadIdx.x; j < NPAD; j += blockDim.x) {
        bool pred = false;
        if (j < K && j > i) {
            float x1j = g_boxoff[j * 4 + 0], y1j = g_boxoff[j * 4 + 1];
            float x2j = g_boxoff[j * 4 + 2], y2j = g_boxoff[j * 4 + 3];
            float xx1 = fmaxf(x1i, x1j), yy1 = fmaxf(y1i, y1j);
            float xx2 = fminf(x2i, x2j), yy2 = fminf(y2i, y2j);
            float iw = fmaxf(1e-28f, __fadd_rn(xx2, -xx1));
            float ih = fmaxf(1e-28f, __fadd_rn(yy2, -yy1));
            float inter = __fmul_rn(iw, ih);
            float den = __fadd_rn(__fadd_rn(__fadd_rn(ai, g_area[j]), -inter), 1e-14f);
            pred = (inter > __fmul_rn(0.6f, den));
        }
        unsigned int b = __ballot_sync(0xffffffffu, pred);
        if ((threadIdx.x & 31) == 0) g_mask[i * 32 + (j >> 5)] = b;
    }
}

// block loads the mask matrix into padded shared (zero-filled tail), warp 0 scans.
__global__ void nms_scan_kernel(int K) {
    extern __shared__ unsigned int sh[];
    int tid = threadIdx.x;
    int totw = K * 32;                     // real words (divisible by 4)
    int padw = NPAD * 32;                  // padded words backing all indices
    uint4* s4 = (uint4*)sh;
    const uint4* gm4 = (const uint4*)g_mask;
    uint4 z4; z4.x = 0u; z4.y = 0u; z4.z = 0u; z4.w = 0u;
    for (int k = tid; k < (padw >> 2); k += blockDim.x)
        s4[k] = (k < (totw >> 2)) ? gm4[k] : z4;
    __syncthreads();
    if (tid >= 32) return;
    int lane = tid;
    unsigned int remv = 0;
    unsigned int valid = g_validmask[lane];
    unsigned int keepw = 0;
    int nch = (K + 31) >> 5;
    for (int c = 0; c < nch; ++c) {
        int base = c << 5;
        int cnt = K - base; if (cnt > 32) cnt = 32;
        unsigned int d[32];
        #pragma unroll
        for (int i = 0; i < 32; i++) d[i] = (i < cnt) ? sh[(base + i) * 32 + c] : 0u;
        unsigned int supp   = __shfl_sync(0xffffffffu, remv, c);
        unsigned int vC     = __shfl_sync(0xffffffffu, valid, c);
        unsigned int aliveM = 0;
        #pragma unroll
        for (int i = 0; i < 32; i++) {
            unsigned int bit = 1u << i;
            if ((vC & bit) && !(supp & bit)) { aliveM |= bit; supp |= d[i]; }
        }
        // fixed-trip predicated accumulation: loads pipeline instead of chaining
        // (safe: sh[] is padded to NPAD rows, tail zero-filled)
        #pragma unroll
        for (int i = 0; i < 32; i++) {
            unsigned int w = sh[(base + i) * 32 + lane];
            if (aliveM & (1u << i)) remv |= w;
        }
        if (lane == c) keepw = aliveM;
    }
    g_keepmask[lane] = keepw;
}

__global__ void output_kernel(float* __restrict__ out, int out_size,
                              const void* fh_ptr, const void* fw_ptr, int K) {
    int t = blockIdx.x * blockDim.x + threadIdx.x;
    if (t < K) {
        bool keep = (g_keepmask[t >> 5] >> (t & 31)) & 1u;
        float m = keep ? 1.0f : 0.0f;
        float W = (float)(read_dim(fw_ptr) * 32);
        float H = (float)(read_dim(fh_ptr) * 32);
        float b0 = g_box[t * 4 + 0], b1 = g_box[t * 4 + 1];
        float b2 = g_box[t * 4 + 2], b3 = g_box[t * 4 + 3];
        float n0 = fminf(fmaxf(__fdiv_rn(b0, W), 0.0f), 1.0f);
        float n1 = fminf(fmaxf(__fdiv_rn(b1, H), 0.0f), 1.0f);
        float n2 = fminf(fmaxf(__fdiv_rn(b2, W), 0.0f), 1.0f);
        float n3 = fminf(fmaxf(__fdiv_rn(b3, H), 0.0f), 1.0f);
        out[t * 4 + 0] = n0 * m;
        out[t * 4 + 1] = n1 * m;
        out[t * 4 + 2] = n2 * m;
        out[t * 4 + 3] = n3 * m;
        out[4 * K + t] = g_topscore[t] * m;
        out[5 * K + t] = keep ? (float)g_toplab[t] : -1.0f;
        out[6 * K + t] = m;
    }
    for (int z = 7 * K + t; z < out_size; z += gridDim.x * blockDim.x) out[z] = 0.0f;
}

// ---------------- launch ----------------
extern "C" void kernel_launch(void* const* d_in, const int* in_sizes, int n_in,
                              void* d_out, int out_size) {
    const float* cls = (const float*)d_in[0];
    const float* reg = (const float*)d_in[1];
    const float* anc = (const float*)d_in[2];
    const void*  fh  = d_in[3];
    const void*  fw  = d_in[4];

    int M = in_sizes[0] / NCLS;
    int A = in_sizes[2] / 2;
    int K = (M < KMAX) ? M : KMAX;

    cudaFuncSetAttribute(rank_kernel, cudaFuncAttributeMaxDynamicSharedMemorySize, CAP * 8);
    cudaFuncSetAttribute(nms_scan_kernel, cudaFuncAttributeMaxDynamicSharedMemorySize, NPAD * 32 * 4);

    zero_kernel<<<64, 256>>>();
    score_kernel<<<(M + 3) / 4, 128>>>(cls, M);
    scan_kernel<<<1, 1024>>>(K);
    hist2_kernel<<<(M + 255) / 256, 256>>>(M);
    scan2_kernel<<<1, 1024>>>(K);
    compact_kernel<<<(M + 255) / 256, 256>>>(M);
    rank_kernel<<<16, 128, CAP * 8>>>(K);
    decode_kernel<<<1, 1024>>>(reg, anc, fw, A, K);
    iou_kernel<<<K, 256>>>(K);
    nms_scan_kernel<<<1, 1024, NPAD * 32 * 4>>>(K);
    output_kernel<<<2, 1024>>>((float*)d_out, out_size, fh, fw, K);
}